// round 7
// baseline (speedup 1.0000x reference)
#include <cuda_runtime.h>

#define HEADS 4
#define C 32
#define F 128
#define NEG_SLOPE 0.02f
#define MAXN 50000
#define MAXE 800000

// Scratch (no allocs allowed)
__device__ int2  g_eij[MAXE];            // packed (i, j) per edge
__device__ int   g_srt[MAXE];            // source j per edge, grouped by target i
__device__ int   g_hist[MAXN];
__device__ int   g_off[MAXN + 1];
__device__ int   g_cur[MAXN];
__device__ float g_s0[MAXN * HEADS];     // dot(x[n,h,:], W[0:32])   (target term)
__device__ float g_s1[MAXN * HEADS];     // dot(x[n,h,:], W[32:64])  (source term)
__device__ float g_denom[MAXN * HEADS];
__device__ int   g_is64;

__device__ __forceinline__ void red_add_v4(float* gptr, float a, float b, float c, float d) {
    asm volatile("red.global.add.v4.f32 [%0], {%1, %2, %3, %4};"
                 :: "l"(gptr), "f"(a), "f"(b), "f"(c), "f"(d) : "memory");
}

__device__ __forceinline__ float lrelu(float a) {
    return a >= 0.f ? a : NEG_SLOPE * a;
}

// Kernel 0: fused init — zero hist + denom; block 0 also detects edge dtype
// (little-endian int64 indices < 50000 => every odd 32-bit word is 0).
__global__ void k_init(const unsigned int* __restrict__ w, int N) {
    int t = blockIdx.x * blockDim.x + threadIdx.x;
    if (t < N) {
        g_hist[t] = 0;
        ((float4*)g_denom)[t] = make_float4(0.f, 0.f, 0.f, 0.f);
    }
    if (blockIdx.x == 0) {
        __shared__ unsigned int acc;
        if (threadIdx.x == 0) acc = 0u;
        __syncthreads();
        unsigned int local = 0u;
        for (int k = threadIdx.x; k < 8192; k += blockDim.x)
            local |= w[2 * k + 1];
        atomicOr(&acc, local);
        __syncthreads();
        if (threadIdx.x == 0) g_is64 = (acc == 0u) ? 1 : 0;
    }
}

// Kernel 1: convert edge_index -> int2 + histogram of targets
__global__ void k_convert(const void* __restrict__ ei, int E) {
    int e = blockIdx.x * blockDim.x + threadIdx.x;
    if (e >= E) return;
    int i, j;
    if (g_is64) {
        const long long* p = (const long long*)ei;
        i = (int)p[e];
        j = (int)p[(size_t)E + e];
    } else {
        const int* p = (const int*)ei;
        i = p[e];
        j = p[E + e];
    }
    g_eij[e] = make_int2(i, j);
    atomicAdd(&g_hist[i], 1);
}

// Kernel 2: scores, warp per node, lane per float4 chunk. Coalesced row reads;
// 8-lane segmented shuffle reduce.
__global__ void k_scores(const float* __restrict__ x, const float* __restrict__ W, int N) {
    int t = blockIdx.x * blockDim.x + threadIdx.x;
    int n = t >> 5;
    int q = t & 31;          // chunk within row; head h = q>>3, c = q&7
    if (n >= N) return;
    float4 v = *(const float4*)(x + (size_t)n * F + q * 4);
    int c = q & 7;
    float4 w0 = ((const float4*)W)[c];
    float4 w1 = ((const float4*)(W + C))[c];
    float p0 = v.x * w0.x + v.y * w0.y + v.z * w0.z + v.w * w0.w;
    float p1 = v.x * w1.x + v.y * w1.y + v.z * w1.z + v.w * w1.w;
#pragma unroll
    for (int o = 4; o; o >>= 1) {
        p0 += __shfl_down_sync(0xFFFFFFFFu, p0, o, 8);
        p1 += __shfl_down_sync(0xFFFFFFFFu, p1, o, 8);
    }
    if (c == 0) {
        int h = q >> 3;
        g_s0[n * 4 + h] = p0;
        g_s1[n * 4 + h] = p1;
    }
}

// Kernel 3: single-block exclusive scan over g_hist -> g_off, g_cur
__global__ void k_scan(int N) {
    __shared__ int sh[1024];
    int tid = threadIdx.x;
    int per = (N + 1023) / 1024;
    int base = tid * per;
    int sum = 0;
    for (int k = 0; k < per; k++)
        if (base + k < N) sum += g_hist[base + k];
    sh[tid] = sum;
    __syncthreads();
    for (int off = 1; off < 1024; off <<= 1) {
        int v = (tid >= off) ? sh[tid - off] : 0;
        __syncthreads();
        sh[tid] += v;
        __syncthreads();
    }
    int run = sh[tid] - sum;
    for (int k = 0; k < per; k++) {
        if (base + k < N) {
            int c = g_hist[base + k];
            g_off[base + k] = run;
            g_cur[base + k] = run;
            run += c;
        }
    }
    if (tid == 1023) g_off[N] = sh[1023];
}

// Kernel 4: scatter sources into CSR order AND accumulate softmax denominators
// (exp without max-shift: |alpha| <~ 11, far from overflow; algebraically equal).
__global__ void k_scatter(int E) {
    int e = blockIdx.x * blockDim.x + threadIdx.x;
    if (e >= E) return;
    int2 ij = g_eij[e];
    int pos = atomicAdd(&g_cur[ij.x], 1);
    g_srt[pos] = ij.y;
    float4 si = *(const float4*)&g_s0[ij.x * 4];
    float4 sj = *(const float4*)&g_s1[ij.y * 4];
    red_add_v4(&g_denom[ij.x * 4],
               __expf(lrelu(si.x + sj.x)), __expf(lrelu(si.y + sj.y)),
               __expf(lrelu(si.z + sj.z)), __expf(lrelu(si.w + sj.w)));
}

// Kernel 5: aggregation, warp per node, lane per float4 chunk.
// Cooperative batched index load (coalesced) + shuffle broadcast => all gather
// addresses known up front, high MLP. Single output write, no atomics.
__global__ void k_agg(const float* __restrict__ x, float* __restrict__ out, int N) {
    int t = blockIdx.x * blockDim.x + threadIdx.x;
    int n = t >> 5;
    int lane = t & 31;
    if (n >= N) return;
    int start = g_off[n];
    int cnt = g_off[n + 1] - start;
    int q = lane;
    int h = q >> 3;
    float s0h = g_s0[n * 4 + h];
    float dh = g_denom[n * 4 + h];
    float rdh = 1.0f / (dh + 1e-16f);
    float4 acc = make_float4(0.f, 0.f, 0.f, 0.f);

    for (int e0 = 0; e0 < cnt; e0 += 32) {
        int batch = min(32, cnt - e0);
        int jv = (lane < batch) ? g_srt[start + e0 + lane] : 0;
#pragma unroll 4
        for (int k = 0; k < batch; k++) {
            int j = __shfl_sync(0xFFFFFFFFu, jv, k);
            float a = lrelu(s0h + g_s1[j * 4 + h]);
            float wgt = __expf(a) * rdh;
            float4 v = *(const float4*)(x + (size_t)j * F + q * 4);
            acc.x += v.x * wgt;
            acc.y += v.y * wgt;
            acc.z += v.z * wgt;
            acc.w += v.w * wgt;
        }
    }
    *(float4*)(out + (size_t)n * F + q * 4) = acc;
}

extern "C" void kernel_launch(void* const* d_in, const int* in_sizes, int n_in,
                              void* d_out, int out_size) {
    const float* x = nullptr;
    const void* ei = nullptr;
    const float* W = nullptr;
    int N = 50000, E = 800000;
    for (int k = 0; k < n_in; k++) {
        int s = in_sizes[k];
        if (s == 64) {
            W = (const float*)d_in[k];
        } else if (s < 4000000) {
            ei = d_in[k];
            E = s / 2;
        } else {
            x = (const float*)d_in[k];
            N = s / F;
        }
    }
    float* out = (float*)d_out;

    const int TB = 256;
    k_init<<<(N + TB - 1) / TB, TB>>>((const unsigned int*)ei, N);
    k_convert<<<(E + TB - 1) / TB, TB>>>(ei, E);
    long long st = (long long)N * 32;
    k_scores<<<(int)((st + TB - 1) / TB), TB>>>(x, W, N);
    k_scan<<<1, 1024>>>(N);
    k_scatter<<<(E + TB - 1) / TB, TB>>>(E);
    k_agg<<<(int)((st + TB - 1) / TB), TB>>>(x, out, N);
}

// round 8
// speedup vs baseline: 1.7566x; 1.7566x over previous
#include <cuda_runtime.h>

#define HEADS 4
#define C 32
#define F 128
#define NEG_SLOPE 0.02f
#define MAXN 50000
#define MAXE 800000
#define SCAN_TILE 1024
#define MAXB ((MAXN + SCAN_TILE - 1) / SCAN_TILE)

// Scratch (no allocs allowed)
__device__ int2  g_eij[MAXE];            // packed (i, j) per edge
__device__ int   g_srt[MAXE];            // source j per edge, grouped by target i
__device__ int   g_hist[MAXN];
__device__ int   g_off[MAXN + 1];
__device__ int   g_cur[MAXN];
__device__ int   g_bsum[MAXB];
__device__ int   g_boff[MAXB];
__device__ float g_s0[MAXN * HEADS];     // dot(x[n,h,:], W[0:32])   (target term)
__device__ float g_s1[MAXN * HEADS];     // dot(x[n,h,:], W[32:64])  (source term)
__device__ float g_denom[MAXN * HEADS];
__device__ int   g_is64;

__device__ __forceinline__ void red_add_v4(float* gptr, float a, float b, float c, float d) {
    asm volatile("red.global.add.v4.f32 [%0], {%1, %2, %3, %4};"
                 :: "l"(gptr), "f"(a), "f"(b), "f"(c), "f"(d) : "memory");
}

__device__ __forceinline__ float lrelu(float a) {
    return a >= 0.f ? a : NEG_SLOPE * a;
}

// Kernel 0: fused init — zero hist + denom; block 0 also detects edge dtype
// (little-endian int64 indices < 50000 => every odd 32-bit word is 0).
__global__ void k_init(const unsigned int* __restrict__ w, int N) {
    int t = blockIdx.x * blockDim.x + threadIdx.x;
    if (t < N) {
        g_hist[t] = 0;
        ((float4*)g_denom)[t] = make_float4(0.f, 0.f, 0.f, 0.f);
    }
    if (blockIdx.x == 0) {
        __shared__ unsigned int acc;
        if (threadIdx.x == 0) acc = 0u;
        __syncthreads();
        unsigned int local = 0u;
        for (int k = threadIdx.x; k < 8192; k += blockDim.x)
            local |= w[2 * k + 1];
        atomicOr(&acc, local);
        __syncthreads();
        if (threadIdx.x == 0) g_is64 = (acc == 0u) ? 1 : 0;
    }
}

// Kernel 1: convert edge_index -> int2 + histogram of targets
__global__ void k_convert(const void* __restrict__ ei, int E) {
    int e = blockIdx.x * blockDim.x + threadIdx.x;
    if (e >= E) return;
    int i, j;
    if (g_is64) {
        const long long* p = (const long long*)ei;
        i = (int)p[e];
        j = (int)p[(size_t)E + e];
    } else {
        const int* p = (const int*)ei;
        i = p[e];
        j = p[E + e];
    }
    g_eij[e] = make_int2(i, j);
    atomicAdd(&g_hist[i], 1);
}

// Kernel 2: scores, warp per node, lane per float4 chunk. Coalesced row reads;
// 8-lane segmented shuffle reduce.
__global__ void k_scores(const float* __restrict__ x, const float* __restrict__ W, int N) {
    int t = blockIdx.x * blockDim.x + threadIdx.x;
    int n = t >> 5;
    int q = t & 31;          // chunk within row; head h = q>>3, c = q&7
    if (n >= N) return;
    float4 v = *(const float4*)(x + (size_t)n * F + q * 4);
    int c = q & 7;
    float4 w0 = ((const float4*)W)[c];
    float4 w1 = ((const float4*)(W + C))[c];
    float p0 = v.x * w0.x + v.y * w0.y + v.z * w0.z + v.w * w0.w;
    float p1 = v.x * w1.x + v.y * w1.y + v.z * w1.z + v.w * w1.w;
#pragma unroll
    for (int o = 4; o; o >>= 1) {
        p0 += __shfl_down_sync(0xFFFFFFFFu, p0, o, 8);
        p1 += __shfl_down_sync(0xFFFFFFFFu, p1, o, 8);
    }
    if (c == 0) {
        int h = q >> 3;
        g_s0[n * 4 + h] = p0;
        g_s1[n * 4 + h] = p1;
    }
}

// Kernel 3a: per-tile exclusive scan (49 blocks in parallel). Writes local
// exclusive prefix into g_off and the tile total into g_bsum.
__global__ void k_scan_local(int N) {
    __shared__ int sh[SCAN_TILE];
    int tid = threadIdx.x;
    int idx = blockIdx.x * SCAN_TILE + tid;
    int v = (idx < N) ? g_hist[idx] : 0;
    sh[tid] = v;
    __syncthreads();
#pragma unroll
    for (int off = 1; off < SCAN_TILE; off <<= 1) {
        int u = (tid >= off) ? sh[tid - off] : 0;
        __syncthreads();
        sh[tid] += u;
        __syncthreads();
    }
    if (idx < N) g_off[idx] = sh[tid] - v;   // exclusive
    if (tid == SCAN_TILE - 1) g_bsum[blockIdx.x] = sh[tid];
}

// Kernel 3b: exclusive scan of tile sums (tiny; one thread is fine)
__global__ void k_scan_block(int NB) {
    if (threadIdx.x == 0) {
        int run = 0;
        for (int b = 0; b < NB; b++) {
            g_boff[b] = run;
            run += g_bsum[b];
        }
        g_boff[NB] = run;   // total (stored in spare slot pattern below)
    }
}

// Kernel 3c: add tile offsets, emit g_cur, set g_off[N]
__global__ void k_scan_add(int N, int NB) {
    int idx = blockIdx.x * SCAN_TILE + threadIdx.x;
    if (idx < N) {
        int o = g_off[idx] + g_boff[blockIdx.x];
        g_off[idx] = o;
        g_cur[idx] = o;
    }
    if (idx == 0) g_off[N] = g_boff[NB];
}

// Kernel 4: scatter sources into CSR order AND accumulate softmax denominators
// (exp without max-shift: |alpha| <~ 11, far from overflow; algebraically equal).
__global__ void k_scatter(int E) {
    int e = blockIdx.x * blockDim.x + threadIdx.x;
    if (e >= E) return;
    int2 ij = g_eij[e];
    int pos = atomicAdd(&g_cur[ij.x], 1);
    g_srt[pos] = ij.y;
    float4 si = *(const float4*)&g_s0[ij.x * 4];
    float4 sj = *(const float4*)&g_s1[ij.y * 4];
    red_add_v4(&g_denom[ij.x * 4],
               __expf(lrelu(si.x + sj.x)), __expf(lrelu(si.y + sj.y)),
               __expf(lrelu(si.z + sj.z)), __expf(lrelu(si.w + sj.w)));
}

// Kernel 5: aggregation, warp per node, lane per float4 chunk.
// Cooperative batched index load (coalesced) + shuffle broadcast => all gather
// addresses known up front, high MLP. Single output write, no atomics.
__global__ void k_agg(const float* __restrict__ x, float* __restrict__ out, int N) {
    int t = blockIdx.x * blockDim.x + threadIdx.x;
    int n = t >> 5;
    int lane = t & 31;
    if (n >= N) return;
    int start = g_off[n];
    int cnt = g_off[n + 1] - start;
    int q = lane;
    int h = q >> 3;
    float s0h = g_s0[n * 4 + h];
    float dh = g_denom[n * 4 + h];
    float rdh = 1.0f / (dh + 1e-16f);
    float4 acc = make_float4(0.f, 0.f, 0.f, 0.f);

    for (int e0 = 0; e0 < cnt; e0 += 32) {
        int batch = min(32, cnt - e0);
        int jv = (lane < batch) ? g_srt[start + e0 + lane] : 0;
#pragma unroll 4
        for (int k = 0; k < batch; k++) {
            int j = __shfl_sync(0xFFFFFFFFu, jv, k);
            float a = lrelu(s0h + g_s1[j * 4 + h]);
            float wgt = __expf(a) * rdh;
            float4 v = *(const float4*)(x + (size_t)j * F + q * 4);
            acc.x += v.x * wgt;
            acc.y += v.y * wgt;
            acc.z += v.z * wgt;
            acc.w += v.w * wgt;
        }
    }
    *(float4*)(out + (size_t)n * F + q * 4) = acc;
}

extern "C" void kernel_launch(void* const* d_in, const int* in_sizes, int n_in,
                              void* d_out, int out_size) {
    const float* x = nullptr;
    const void* ei = nullptr;
    const float* W = nullptr;
    int N = 50000, E = 800000;
    for (int k = 0; k < n_in; k++) {
        int s = in_sizes[k];
        if (s == 64) {
            W = (const float*)d_in[k];
        } else if (s < 4000000) {
            ei = d_in[k];
            E = s / 2;
        } else {
            x = (const float*)d_in[k];
            N = s / F;
        }
    }
    float* out = (float*)d_out;

    const int TB = 256;
    int NB = (N + SCAN_TILE - 1) / SCAN_TILE;
    k_init<<<(N + TB - 1) / TB, TB>>>((const unsigned int*)ei, N);
    k_convert<<<(E + TB - 1) / TB, TB>>>(ei, E);
    long long st = (long long)N * 32;
    k_scores<<<(int)((st + TB - 1) / TB), TB>>>(x, W, N);
    k_scan_local<<<NB, SCAN_TILE>>>(N);
    k_scan_block<<<1, 32>>>(NB);
    k_scan_add<<<NB, SCAN_TILE>>>(N, NB);
    k_scatter<<<(E + TB - 1) / TB, TB>>>(E);
    k_agg<<<(int)((st + TB - 1) / TB), TB>>>(x, out, N);
}

// round 9
// speedup vs baseline: 1.9862x; 1.1307x over previous
#include <cuda_runtime.h>

#define HEADS 4
#define C 32
#define F 128
#define NEG_SLOPE 0.02f
#define MAXN 50000
#define MAXE 800000
#define SCAN_TILE 1024
#define MAXB ((MAXN + SCAN_TILE - 1) / SCAN_TILE)

// Scratch (no allocs allowed)
__device__ int   g_srt[MAXE];            // source j per edge, grouped by target i
__device__ int   g_hist[MAXN];
__device__ int   g_off[MAXN + 1];
__device__ int   g_cur[MAXN];
__device__ int   g_bsum[MAXB];
__device__ float g_s0[MAXN * HEADS];     // dot(x[n,h,:], W[0:32])   (target term)
__device__ float g_s1[MAXN * HEADS];     // dot(x[n,h,:], W[32:64])  (source term)
__device__ int   g_is64;

__device__ __forceinline__ float lrelu(float a) {
    return a >= 0.f ? a : NEG_SLOPE * a;
}

// Kernel 0: zero hist; block 0 also detects edge dtype
// (little-endian int64 indices < 50000 => every odd 32-bit word is 0).
__global__ void k_init(const unsigned int* __restrict__ w, int N) {
    int t = blockIdx.x * blockDim.x + threadIdx.x;
    if (t < N) g_hist[t] = 0;
    if (blockIdx.x == 0) {
        __shared__ unsigned int acc;
        if (threadIdx.x == 0) acc = 0u;
        __syncthreads();
        unsigned int local = 0u;
        for (int k = threadIdx.x; k < 8192; k += blockDim.x)
            local |= w[2 * k + 1];
        atomicOr(&acc, local);
        __syncthreads();
        if (threadIdx.x == 0) g_is64 = (acc == 0u) ? 1 : 0;
    }
}

// Kernel 1: histogram of targets (reads only the i-half of edge_index)
__global__ void k_hist(const void* __restrict__ ei, int E) {
    int e = blockIdx.x * blockDim.x + threadIdx.x;
    if (e >= E) return;
    int i = g_is64 ? (int)((const long long*)ei)[e] : ((const int*)ei)[e];
    atomicAdd(&g_hist[i], 1);
}

// Kernel 2: scores, warp per node, lane per float4 chunk. Coalesced row reads;
// 8-lane segmented shuffle reduce.
__global__ void k_scores(const float* __restrict__ x, const float* __restrict__ W, int N) {
    int t = blockIdx.x * blockDim.x + threadIdx.x;
    int n = t >> 5;
    int q = t & 31;          // chunk within row; head h = q>>3, c = q&7
    if (n >= N) return;
    float4 v = *(const float4*)(x + (size_t)n * F + q * 4);
    int c = q & 7;
    float4 w0 = ((const float4*)W)[c];
    float4 w1 = ((const float4*)(W + C))[c];
    float p0 = v.x * w0.x + v.y * w0.y + v.z * w0.z + v.w * w0.w;
    float p1 = v.x * w1.x + v.y * w1.y + v.z * w1.z + v.w * w1.w;
#pragma unroll
    for (int o = 4; o; o >>= 1) {
        p0 += __shfl_down_sync(0xFFFFFFFFu, p0, o, 8);
        p1 += __shfl_down_sync(0xFFFFFFFFu, p1, o, 8);
    }
    if (c == 0) {
        int h = q >> 3;
        g_s0[n * 4 + h] = p0;
        g_s1[n * 4 + h] = p1;
    }
}

// Kernel 3a: per-tile exclusive scan (49 blocks in parallel). Writes local
// exclusive prefix into g_off and the tile total into g_bsum.
__global__ void k_scan_local(int N) {
    __shared__ int sh[SCAN_TILE];
    int tid = threadIdx.x;
    int idx = blockIdx.x * SCAN_TILE + tid;
    int v = (idx < N) ? g_hist[idx] : 0;
    sh[tid] = v;
    __syncthreads();
#pragma unroll
    for (int off = 1; off < SCAN_TILE; off <<= 1) {
        int u = (tid >= off) ? sh[tid - off] : 0;
        __syncthreads();
        sh[tid] += u;
        __syncthreads();
    }
    if (idx < N) g_off[idx] = sh[tid] - v;   // exclusive
    if (tid == SCAN_TILE - 1) g_bsum[blockIdx.x] = sh[tid];
}

// Kernel 3b: add tile offsets (each block sums the preceding <=49 tile sums
// itself — no middle kernel), emit g_cur, set g_off[N].
__global__ void k_scan_add(int N, int NB) {
    __shared__ int boff;
    if (threadIdx.x == 0) {
        int run = 0;
        for (int b = 0; b < blockIdx.x; b++) run += g_bsum[b];
        boff = run;
        if (blockIdx.x == NB - 1) g_off[N] = run + g_bsum[NB - 1];
    }
    __syncthreads();
    int idx = blockIdx.x * SCAN_TILE + threadIdx.x;
    if (idx < N) {
        int o = g_off[idx] + boff;
        g_off[idx] = o;
        g_cur[idx] = o;
    }
}

// Kernel 4: scatter sources into CSR order (reads raw edge list directly)
__global__ void k_scatter(const void* __restrict__ ei, int E) {
    int e = blockIdx.x * blockDim.x + threadIdx.x;
    if (e >= E) return;
    int i, j;
    if (g_is64) {
        const long long* p = (const long long*)ei;
        i = (int)p[e];
        j = (int)p[(size_t)E + e];
    } else {
        const int* p = (const int*)ei;
        i = p[e];
        j = p[E + e];
    }
    int pos = atomicAdd(&g_cur[i], 1);
    g_srt[pos] = j;
}

// Kernel 5: aggregation, warp per node, lane per float4 chunk.
// Accumulates BOTH the unnormalized weighted sum and the softmax denominator
// in one walk (every lane sees every edge), scaling once at the end:
//   out = (sum_e exp(a_e) * v_e) / (sum_e exp(a_e) + 1e-16)
__global__ void k_agg(const float* __restrict__ x, float* __restrict__ out, int N) {
    int t = blockIdx.x * blockDim.x + threadIdx.x;
    int n = t >> 5;
    int lane = t & 31;
    if (n >= N) return;
    int start = g_off[n];
    int cnt = g_off[n + 1] - start;
    int q = lane;
    int h = q >> 3;
    float s0h = g_s0[n * 4 + h];
    float d = 0.f;
    float4 acc = make_float4(0.f, 0.f, 0.f, 0.f);

    for (int e0 = 0; e0 < cnt; e0 += 32) {
        int batch = min(32, cnt - e0);
        int jv = (lane < batch) ? g_srt[start + e0 + lane] : 0;
#pragma unroll 8
        for (int k = 0; k < batch; k++) {
            int j = __shfl_sync(0xFFFFFFFFu, jv, k);
            float a = lrelu(s0h + g_s1[j * 4 + h]);
            float wgt = __expf(a);
            d += wgt;
            float4 v = *(const float4*)(x + (size_t)j * F + q * 4);
            acc.x += v.x * wgt;
            acc.y += v.y * wgt;
            acc.z += v.z * wgt;
            acc.w += v.w * wgt;
        }
    }
    float rdh = __fdividef(1.0f, d + 1e-16f);
    acc.x *= rdh; acc.y *= rdh; acc.z *= rdh; acc.w *= rdh;
    *(float4*)(out + (size_t)n * F + q * 4) = acc;
}

extern "C" void kernel_launch(void* const* d_in, const int* in_sizes, int n_in,
                              void* d_out, int out_size) {
    const float* x = nullptr;
    const void* ei = nullptr;
    const float* W = nullptr;
    int N = 50000, E = 800000;
    for (int k = 0; k < n_in; k++) {
        int s = in_sizes[k];
        if (s == 64) {
            W = (const float*)d_in[k];
        } else if (s < 4000000) {
            ei = d_in[k];
            E = s / 2;
        } else {
            x = (const float*)d_in[k];
            N = s / F;
        }
    }
    float* out = (float*)d_out;

    const int TB = 256;
    int NB = (N + SCAN_TILE - 1) / SCAN_TILE;
    k_init<<<(N + TB - 1) / TB, TB>>>((const unsigned int*)ei, N);
    k_hist<<<(E + TB - 1) / TB, TB>>>(ei, E);
    long long st = (long long)N * 32;
    k_scores<<<(int)((st + TB - 1) / TB), TB>>>(x, W, N);
    k_scan_local<<<NB, SCAN_TILE>>>(N);
    k_scan_add<<<NB, SCAN_TILE>>>(N, NB);
    k_scatter<<<(E + TB - 1) / TB, TB>>>(ei, E);
    k_agg<<<(int)((st + TB - 1) / TB), TB>>>(x, out, N);
}

// round 10
// speedup vs baseline: 2.1546x; 1.0848x over previous
#include <cuda_runtime.h>
#include <cuda_fp16.h>

#define HEADS 4
#define C 32
#define F 128
#define NEG_SLOPE 0.02f
#define MAXN 50000
#define MAXE 800000
#define SCAN_TILE 1024
#define MAXB ((MAXN + SCAN_TILE - 1) / SCAN_TILE)

// Scratch (no allocs allowed)
__device__ int    g_srt[MAXE];            // source j per edge, grouped by target i
__device__ int    g_hist[MAXN];
__device__ int    g_off[MAXN + 1];
__device__ int    g_cur[MAXN];
__device__ int    g_bsum[MAXB];
__device__ float  g_s0[MAXN * HEADS];     // dot(x[n,h,:], W[0:32])   (target term)
__device__ float  g_s1[MAXN * HEADS];     // dot(x[n,h,:], W[32:64])  (source term)
__device__ __half g_xh[MAXN * F];         // fp16 mirror of x (halves gather bytes)
__device__ int    g_is64;

__device__ __forceinline__ float lrelu(float a) {
    return a >= 0.f ? a : NEG_SLOPE * a;
}

// Kernel 0: zero hist; block 0 also detects edge dtype
// (little-endian int64 indices < 50000 => every odd 32-bit word is 0).
__global__ void k_init(const unsigned int* __restrict__ w, int N) {
    int t = blockIdx.x * blockDim.x + threadIdx.x;
    if (t < N) g_hist[t] = 0;
    if (blockIdx.x == 0) {
        __shared__ unsigned int acc;
        if (threadIdx.x == 0) acc = 0u;
        __syncthreads();
        unsigned int local = 0u;
        for (int k = threadIdx.x; k < 8192; k += blockDim.x)
            local |= w[2 * k + 1];
        atomicOr(&acc, local);
        __syncthreads();
        if (threadIdx.x == 0) g_is64 = (acc == 0u) ? 1 : 0;
    }
}

// Kernel 1: histogram of targets (reads only the i-half of edge_index)
__global__ void k_hist(const void* __restrict__ ei, int E) {
    int e = blockIdx.x * blockDim.x + threadIdx.x;
    if (e >= E) return;
    int i = g_is64 ? (int)((const long long*)ei)[e] : ((const int*)ei)[e];
    atomicAdd(&g_hist[i], 1);
}

// Kernel 2: scores + fp16 mirror. Warp per node, lane per float4 chunk.
// Coalesced row reads; 8-lane segmented shuffle reduce; each lane also writes
// its 4 channels as fp16 (coalesced 8B/lane).
__global__ void k_scores(const float* __restrict__ x, const float* __restrict__ W, int N) {
    int t = blockIdx.x * blockDim.x + threadIdx.x;
    int n = t >> 5;
    int q = t & 31;          // chunk within row; head h = q>>3, c = q&7
    if (n >= N) return;
    float4 v = *(const float4*)(x + (size_t)n * F + q * 4);

    // fp16 mirror: 4 halves = 8 bytes per lane
    __half2 h0 = __floats2half2_rn(v.x, v.y);
    __half2 h1 = __floats2half2_rn(v.z, v.w);
    *(__half2*)(g_xh + (size_t)n * F + q * 4) = h0;
    *(__half2*)(g_xh + (size_t)n * F + q * 4 + 2) = h1;

    int c = q & 7;
    float4 w0 = ((const float4*)W)[c];
    float4 w1 = ((const float4*)(W + C))[c];
    float p0 = v.x * w0.x + v.y * w0.y + v.z * w0.z + v.w * w0.w;
    float p1 = v.x * w1.x + v.y * w1.y + v.z * w1.z + v.w * w1.w;
#pragma unroll
    for (int o = 4; o; o >>= 1) {
        p0 += __shfl_down_sync(0xFFFFFFFFu, p0, o, 8);
        p1 += __shfl_down_sync(0xFFFFFFFFu, p1, o, 8);
    }
    if (c == 0) {
        int h = q >> 3;
        g_s0[n * 4 + h] = p0;
        g_s1[n * 4 + h] = p1;
    }
}

// Kernel 3a: per-tile exclusive scan (49 blocks in parallel).
__global__ void k_scan_local(int N) {
    __shared__ int sh[SCAN_TILE];
    int tid = threadIdx.x;
    int idx = blockIdx.x * SCAN_TILE + tid;
    int v = (idx < N) ? g_hist[idx] : 0;
    sh[tid] = v;
    __syncthreads();
#pragma unroll
    for (int off = 1; off < SCAN_TILE; off <<= 1) {
        int u = (tid >= off) ? sh[tid - off] : 0;
        __syncthreads();
        sh[tid] += u;
        __syncthreads();
    }
    if (idx < N) g_off[idx] = sh[tid] - v;   // exclusive
    if (tid == SCAN_TILE - 1) g_bsum[blockIdx.x] = sh[tid];
}

// Kernel 3b: add tile offsets (each block sums preceding tile sums itself),
// emit g_cur, set g_off[N].
__global__ void k_scan_add(int N, int NB) {
    __shared__ int boff;
    if (threadIdx.x == 0) {
        int run = 0;
        for (int b = 0; b < blockIdx.x; b++) run += g_bsum[b];
        boff = run;
        if (blockIdx.x == NB - 1) g_off[N] = run + g_bsum[NB - 1];
    }
    __syncthreads();
    int idx = blockIdx.x * SCAN_TILE + threadIdx.x;
    if (idx < N) {
        int o = g_off[idx] + boff;
        g_off[idx] = o;
        g_cur[idx] = o;
    }
}

// Kernel 4: scatter sources into CSR order (reads raw edge list directly)
__global__ void k_scatter(const void* __restrict__ ei, int E) {
    int e = blockIdx.x * blockDim.x + threadIdx.x;
    if (e >= E) return;
    int i, j;
    if (g_is64) {
        const long long* p = (const long long*)ei;
        i = (int)p[e];
        j = (int)p[(size_t)E + e];
    } else {
        const int* p = (const int*)ei;
        i = p[e];
        j = p[E + e];
    }
    int pos = atomicAdd(&g_cur[i], 1);
    g_srt[pos] = j;
}

// Kernel 5: aggregation, warp per node, lane owns 4 channels (8B fp16 gather).
// Accumulates unnormalized weighted sum + softmax denominator in one walk:
//   out = (sum_e exp(a_e) * v_e) / (sum_e exp(a_e) + 1e-16)
__global__ void k_agg(float* __restrict__ out, int N) {
    int t = blockIdx.x * blockDim.x + threadIdx.x;
    int n = t >> 5;
    int lane = t & 31;
    if (n >= N) return;
    int start = g_off[n];
    int cnt = g_off[n + 1] - start;
    int q = lane;            // channel group: channels [q*4, q*4+4); head = q>>3
    int h = q >> 3;
    float s0h = g_s0[n * 4 + h];
    float d = 0.f;
    float4 acc = make_float4(0.f, 0.f, 0.f, 0.f);

    for (int e0 = 0; e0 < cnt; e0 += 32) {
        int batch = min(32, cnt - e0);
        int jv = (lane < batch) ? g_srt[start + e0 + lane] : 0;
#pragma unroll 8
        for (int k = 0; k < batch; k++) {
            int j = __shfl_sync(0xFFFFFFFFu, jv, k);
            float a = lrelu(s0h + g_s1[j * 4 + h]);
            float wgt = __expf(a);
            d += wgt;
            uint2 raw = *(const uint2*)(g_xh + (size_t)j * F + q * 4);
            float2 v01 = __half22float2(*(__half2*)&raw.x);
            float2 v23 = __half22float2(*(__half2*)&raw.y);
            acc.x += v01.x * wgt;
            acc.y += v01.y * wgt;
            acc.z += v23.x * wgt;
            acc.w += v23.y * wgt;
        }
    }
    float rdh = __fdividef(1.0f, d + 1e-16f);
    acc.x *= rdh; acc.y *= rdh; acc.z *= rdh; acc.w *= rdh;
    *(float4*)(out + (size_t)n * F + q * 4) = acc;
}

extern "C" void kernel_launch(void* const* d_in, const int* in_sizes, int n_in,
                              void* d_out, int out_size) {
    const float* x = nullptr;
    const void* ei = nullptr;
    const float* W = nullptr;
    int N = 50000, E = 800000;
    for (int k = 0; k < n_in; k++) {
        int s = in_sizes[k];
        if (s == 64) {
            W = (const float*)d_in[k];
        } else if (s < 4000000) {
            ei = d_in[k];
            E = s / 2;
        } else {
            x = (const float*)d_in[k];
            N = s / F;
        }
    }
    float* out = (float*)d_out;

    const int TB = 256;
    int NB = (N + SCAN_TILE - 1) / SCAN_TILE;
    k_init<<<(N + TB - 1) / TB, TB>>>((const unsigned int*)ei, N);
    k_hist<<<(E + TB - 1) / TB, TB>>>(ei, E);
    long long st = (long long)N * 32;
    k_scores<<<(int)((st + TB - 1) / TB), TB>>>(x, W, N);
    k_scan_local<<<NB, SCAN_TILE>>>(N);
    k_scan_add<<<NB, SCAN_TILE>>>(N, NB);
    k_scatter<<<(E + TB - 1) / TB, TB>>>(ei, E);
    k_agg<<<(int)((st + TB - 1) / TB), TB>>>(out, N);
}